// round 3
// baseline (speedup 1.0000x reference)
#include <cuda_runtime.h>

#define NW      10
#define DIM     1024
#define THREADS 128

typedef unsigned long long ull;

// ---------- packed f32x2 helpers ----------
__device__ __forceinline__ ull pk(float lo, float hi) {
    ull r;
    asm("mov.b64 %0, {%1, %2};" : "=l"(r)
        : "r"(__float_as_uint(lo)), "r"(__float_as_uint(hi)));
    return r;
}
__device__ __forceinline__ void upk(ull v, float& lo, float& hi) {
    unsigned a, b;
    asm("mov.b64 {%0, %1}, %2;" : "=r"(a), "=r"(b) : "l"(v));
    lo = __uint_as_float(a); hi = __uint_as_float(b);
}
__device__ __forceinline__ ull swp(ull v) {
    float lo, hi; upk(v, lo, hi); return pk(hi, lo);
}
__device__ __forceinline__ ull fma2(ull a, ull b, ull c) {
    ull d;
    asm("fma.rn.f32x2 %0, %1, %2, %3;" : "=l"(d) : "l"(a), "l"(b), "l"(c));
    return d;
}
__device__ __forceinline__ ull mul2(ull a, ull b) {
    ull d;
    asm("mul.rn.f32x2 %0, %1, %2;" : "=l"(d) : "l"(a), "l"(b));
    return d;
}

// ---------- gate coefficients (packed pairs, computed per launch) ----------
// d_g1[j]: 8 ull = {a2=(ar,ar), ai2=(-ai,ai), b2=(br,br), bi2=(-bi,bi),
//                   c2=(cr,cr), ci2=(-ci,ci), d2=(dr,dr), di2=(-di,di)}
// d_g2[j]: 3 ull = {c2=(c,c), s2=(s,s), ns2=(-s,-s)}
__device__ float d_g1[NW][16];
__device__ float d_g2[NW][6];

__global__ void qsa_prep(const float* __restrict__ rx0,
                         const float* __restrict__ ry0,
                         const float* __restrict__ ry1) {
    int j = threadIdx.x;
    if (j < NW) {
        float c1, s1, c2, s2, c3, s3;
        sincosf(0.5f * rx0[j], &s1, &c1);
        sincosf(0.5f * ry0[j], &s2, &c2);
        sincosf(0.5f * ry1[j], &s3, &c3);
        // G = RY(ry0)@RX(rx0): a = c1c2 + i s1s2 ; b = -s2c1 - i s1c2 ;
        //                      c = s2c1 - i s1c2 ; d = c1c2 - i s1s2
        float ar =  c1 * c2, ai =  s1 * s2;
        float br = -s2 * c1, bi = -s1 * c2;
        float cr =  s2 * c1, ci = -s1 * c2;
        float dr =  c1 * c2, di = -s1 * s2;
        float* g = d_g1[j];
        g[0]  = ar;  g[1]  = ar;   g[2]  = -ai; g[3]  = ai;
        g[4]  = br;  g[5]  = br;   g[6]  = -bi; g[7]  = bi;
        g[8]  = cr;  g[9]  = cr;   g[10] = -ci; g[11] = ci;
        g[12] = dr;  g[13] = dr;   g[14] = -di; g[15] = di;
        float* h = d_g2[j];
        h[0] = c3; h[1] = c3; h[2] = s3; h[3] = s3; h[4] = -s3; h[5] = -s3;
    }
}

// ---------- gate kernels on packed state ----------
// Complex 2x2 on register bit kb.
__device__ __forceinline__ void cgate_reg(ull* r, const ull* g, const int kb) {
    const ull a2 = g[0], ai2 = g[1], b2 = g[2], bi2 = g[3];
    const ull c2 = g[4], ci2 = g[5], d2 = g[6], di2 = g[7];
#pragma unroll
    for (int m = 0; m < 8; m++) {
        if ((m >> kb) & 1) continue;
        const int k1 = m | (1 << kb);
        ull u = r[m], v = r[k1];
        ull us = swp(u), vs = swp(v);
        r[m]  = fma2(a2, u, fma2(ai2, us, fma2(b2, v, mul2(bi2, vs))));
        r[k1] = fma2(c2, u, fma2(ci2, us, fma2(d2, v, mul2(di2, vs))));
    }
}

// Complex 2x2 on lane bit lb via shuffle.
__device__ __forceinline__ void cgate_shfl(ull* r, const ull* g,
                                           const int lb, const int lane) {
    const bool hi = (lane >> lb) & 1;
    const ull p2  = hi ? g[6] : g[0];
    const ull pi2 = hi ? g[7] : g[1];
    const ull q2  = hi ? g[4] : g[2];
    const ull qi2 = hi ? g[5] : g[3];
#pragma unroll
    for (int k = 0; k < 8; k++) {
        float ux, uy; upk(r[k], ux, uy);
        float vx = __shfl_xor_sync(0xffffffffu, ux, 1 << lb);
        float vy = __shfl_xor_sync(0xffffffffu, uy, 1 << lb);
        r[k] = fma2(p2, r[k],
               fma2(pi2, pk(uy, ux),
               fma2(q2, pk(vx, vy), mul2(qi2, pk(vy, vx)))));
    }
}

// Real RY on register bit kb.
__device__ __forceinline__ void rgate_reg(ull* r, const ull* g, const int kb) {
    const ull c2 = g[0], s2 = g[1], ns2 = g[2];
#pragma unroll
    for (int m = 0; m < 8; m++) {
        if ((m >> kb) & 1) continue;
        const int k1 = m | (1 << kb);
        ull u = r[m], v = r[k1];
        r[m]  = fma2(c2, u, mul2(ns2, v));
        r[k1] = fma2(c2, v, mul2(s2, u));
    }
}

// Real RY on lane bit lb via shuffle.
__device__ __forceinline__ void rgate_shfl(ull* r, const ull* g,
                                           const int lb, const int lane) {
    const bool hi = (lane >> lb) & 1;
    const ull c2 = g[0];
    const ull q2 = hi ? g[1] : g[2];   // +s for hi half, -s for lo half
#pragma unroll
    for (int k = 0; k < 8; k++) {
        float ux, uy; upk(r[k], ux, uy);
        float vx = __shfl_xor_sync(0xffffffffu, ux, 1 << lb);
        float vy = __shfl_xor_sync(0xffffffffu, uy, 1 << lb);
        r[k] = fma2(c2, r[k], mul2(q2, pk(vx, vy)));
    }
}

__global__ __launch_bounds__(THREADS)
void qsa_main(const float* __restrict__ x, float* __restrict__ out) {
    __shared__ ull   buf0[DIM];
    __shared__ ull   buf1[DIM];
    __shared__ ull   sg1[NW * 8];
    __shared__ ull   sg2[NW * 3];
    __shared__ float swred[4 * NW];
    __shared__ float s_inv2;

    const int t    = threadIdx.x;
    const int lane = t & 31;
    const int w    = t >> 5;
    const int row  = blockIdx.x;

    if (t < NW * 8) sg1[t] = ((const ull*)d_g1)[t];
    if (t < NW * 3) sg2[t] = ((const ull*)d_g2)[t];

    // ---- Load (layout A: i = t + 128k; lane=bits0-4, warp=bits5-6, k=bits7-9) ----
    ull r[8];
    float ss = 0.f;
    const float* xr = x + (size_t)row * DIM;
#pragma unroll
    for (int k = 0; k < 8; k++) {
        float v = __ldg(xr + t + THREADS * k);
        r[k] = pk(v, 0.f);
        ss += v * v;
    }
#pragma unroll
    for (int o = 16; o; o >>= 1) ss += __shfl_xor_sync(0xffffffffu, ss, o);
    if (lane == 0) swred[w] = ss;
    __syncthreads();                                   // sync0 (covers sg preload)
    if (t == 0) {
        float s = swred[0] + swred[1] + swred[2] + swred[3];
        s_inv2 = 1.f / fmaxf(s, 1e-24f);               // == 1/max(norm,1e-12)^2
    }

    // ======== Layer 1 (fused complex RY*RX per wire) ========
    cgate_reg(r, sg1 + 8 * 0, 2);       // q0 <-> bit9 (k bit2)
    cgate_reg(r, sg1 + 8 * 1, 1);       // q1 <-> bit8
    cgate_reg(r, sg1 + 8 * 2, 0);       // q2 <-> bit7
    cgate_shfl(r, sg1 + 8 * 5, 4, lane);// q5 <-> bit4
    cgate_shfl(r, sg1 + 8 * 6, 3, lane);
    cgate_shfl(r, sg1 + 8 * 7, 2, lane);
    cgate_shfl(r, sg1 + 8 * 8, 1, lane);
    cgate_shfl(r, sg1 + 8 * 9, 0, lane);// q9 <-> bit0

    // ---- Exchange A -> B (layout B: i = lane | (k<<5) | (w<<8)) ----
#pragma unroll
    for (int k = 0; k < 8; k++) buf0[t + THREADS * k] = r[k];
    __syncthreads();                                   // sync1
#pragma unroll
    for (int k = 0; k < 8; k++) r[k] = buf0[lane | (k << 5) | (w << 8)];

    cgate_reg(r, sg1 + 8 * 4, 0);       // q4 <-> bit5 (k bit0)
    cgate_reg(r, sg1 + 8 * 3, 1);       // q3 <-> bit6

    // ---- CNOT ring (fixed suffix-XOR permutation), fused with exchange B -> A ----
#pragma unroll
    for (int k = 0; k < 8; k++) {
        unsigned i = (unsigned)(lane | (k << 5) | (w << 8));
        unsigned y = i;
        y ^= y >> 1; y ^= y >> 2; y ^= y >> 4; y ^= y >> 8;
        unsigned dst = (y & 0x1FFu) | (((y ^ (i >> 9)) & 1u) << 9);
        buf1[dst] = r[k];
    }
    __syncthreads();                                   // sync2
#pragma unroll
    for (int k = 0; k < 8; k++) r[k] = buf1[t + THREADS * k];

    // ======== Layer 2 (real RY per wire) ========
    rgate_reg(r, sg2 + 3 * 0, 2);
    rgate_reg(r, sg2 + 3 * 1, 1);
    rgate_reg(r, sg2 + 3 * 2, 0);
    rgate_shfl(r, sg2 + 3 * 5, 4, lane);
    rgate_shfl(r, sg2 + 3 * 6, 3, lane);
    rgate_shfl(r, sg2 + 3 * 7, 2, lane);
    rgate_shfl(r, sg2 + 3 * 8, 1, lane);
    rgate_shfl(r, sg2 + 3 * 9, 0, lane);

    // ---- Exchange A -> B again ----
#pragma unroll
    for (int k = 0; k < 8; k++) buf0[t + THREADS * k] = r[k];
    __syncthreads();                                   // sync3
#pragma unroll
    for (int k = 0; k < 8; k++) r[k] = buf0[lane | (k << 5) | (w << 8)];

    rgate_reg(r, sg2 + 3 * 4, 0);       // q4
    rgate_reg(r, sg2 + 3 * 3, 1);       // q3

    // ======== <Z_j> reduction (layout B: bits5-7 = k; 8,9 = w; 0-4 = lane) ====
    float tot = 0.f, a2 = 0.f, a3 = 0.f, a4 = 0.f;
#pragma unroll
    for (int k = 0; k < 8; k++) {
        float px, py; upk(r[k], px, py);
        float p = px * px + py * py;
        tot += p;
        a4 += (k & 1) ? -p : p;   // q4 <-> bit5 (k bit0)
        a3 += (k & 2) ? -p : p;   // q3 <-> bit6
        a2 += (k & 4) ? -p : p;   // q2 <-> bit7
    }
    // Spawning sum/difference tree over lane bits: d_b = signed sum for lane bit b.
    float s = tot, d4, d3, d2v, d1, d0;
    {
        float n = __shfl_xor_sync(0xffffffffu, s, 16);
        d4 = (lane & 16) ? n - s : s - n; s += n;
    }
    {
        float n = __shfl_xor_sync(0xffffffffu, s, 8);
        d3 = (lane & 8) ? n - s : s - n; s += n;
        d4 += __shfl_xor_sync(0xffffffffu, d4, 8);
    }
    {
        float n = __shfl_xor_sync(0xffffffffu, s, 4);
        d2v = (lane & 4) ? n - s : s - n; s += n;
        d4 += __shfl_xor_sync(0xffffffffu, d4, 4);
        d3 += __shfl_xor_sync(0xffffffffu, d3, 4);
    }
    {
        float n = __shfl_xor_sync(0xffffffffu, s, 2);
        d1 = (lane & 2) ? n - s : s - n; s += n;
        d4 += __shfl_xor_sync(0xffffffffu, d4, 2);
        d3 += __shfl_xor_sync(0xffffffffu, d3, 2);
        d2v += __shfl_xor_sync(0xffffffffu, d2v, 2);
    }
    {
        float n = __shfl_xor_sync(0xffffffffu, s, 1);
        d0 = (lane & 1) ? n - s : s - n; s += n;
        d4 += __shfl_xor_sync(0xffffffffu, d4, 1);
        d3 += __shfl_xor_sync(0xffffffffu, d3, 1);
        d2v += __shfl_xor_sync(0xffffffffu, d2v, 1);
        d1 += __shfl_xor_sync(0xffffffffu, d1, 1);
    }
    // a2,a3,a4: plain 5-step reductions
#pragma unroll
    for (int o = 16; o; o >>= 1) {
        a2 += __shfl_xor_sync(0xffffffffu, a2, o);
        a3 += __shfl_xor_sync(0xffffffffu, a3, o);
        a4 += __shfl_xor_sync(0xffffffffu, a4, o);
    }
    if (lane == 0) {
        // q0 <-> bit9 = w bit1 ; q1 <-> bit8 = w bit0 (uniform per warp)
        swred[w * NW + 0] = ((w >> 1) & 1) ? -s : s;
        swred[w * NW + 1] = ( w       & 1) ? -s : s;
        swred[w * NW + 2] = a2;
        swred[w * NW + 3] = a3;
        swred[w * NW + 4] = a4;
        swred[w * NW + 5] = d4;   // q5 <-> bit4
        swred[w * NW + 6] = d3;
        swred[w * NW + 7] = d2v;
        swred[w * NW + 8] = d1;
        swred[w * NW + 9] = d0;   // q9 <-> bit0
    }
    __syncthreads();                                   // sync4
    if (t < NW) {
        float e = swred[t] + swred[NW + t] + swred[2 * NW + t] + swred[3 * NW + t];
        out[(size_t)row * NW + t] = e * s_inv2;
    }
}

extern "C" void kernel_launch(void* const* d_in, const int* in_sizes, int n_in,
                              void* d_out, int out_size) {
    const float* x   = (const float*)d_in[0];
    const float* rx0 = (const float*)d_in[1];
    const float* ry0 = (const float*)d_in[2];
    const float* ry1 = (const float*)d_in[3];
    float* out = (float*)d_out;

    int nrows = in_sizes[0] / DIM;  // 4096

    qsa_prep<<<1, 32>>>(rx0, ry0, ry1);
    qsa_main<<<nrows, THREADS>>>(x, out);
}